// round 1
// baseline (speedup 1.0000x reference)
#include <cuda_runtime.h>
#include <cuda_bf16.h>
#include <math.h>

// Problem constants (fixed by the dataset)
#define NNODES 100000
#define NFEAT  128
#define NHID   64
#define NCLASS 16

// Scratch: float4 arrays guarantee 16B alignment for vector red.
__device__ float4 g_sup1[NNODES * (NHID / 4)];    // N x 64  (x @ W1)
__device__ float4 g_agg1[NNODES * (NHID / 4)];    // N x 64  (adj @ sup1)
__device__ float4 g_sup2[NNODES * (NCLASS / 4)];  // N x 16  (h @ W2)
__device__ float4 g_agg2[NNODES * (NCLASS / 4)];  // N x 16  (adj @ sup2)

// ---------------------------------------------------------------------------
// GEMM1: out[N,64] = x[N,128] @ W1[128,64]. One warp per row.
// Lane j accumulates cols {2j, 2j+1}; x row values broadcast via shfl.
// ---------------------------------------------------------------------------
__global__ void gemm1_kernel(const float* __restrict__ x,
                             const float* __restrict__ W1,
                             float* __restrict__ out, int N) {
    __shared__ float sW[NFEAT * NHID];  // 32 KB
    for (int i = threadIdx.x; i < NFEAT * NHID; i += blockDim.x) sW[i] = W1[i];
    __syncthreads();

    int warp = (blockIdx.x * blockDim.x + threadIdx.x) >> 5;
    int lane = threadIdx.x & 31;
    if (warp >= N) return;

    const float* xr = x + (size_t)warp * NFEAT;
    float acc0 = 0.f, acc1 = 0.f;
#pragma unroll
    for (int kk = 0; kk < NFEAT; kk += 32) {
        float xv = xr[kk + lane];
#pragma unroll
        for (int t = 0; t < 32; t++) {
            float xs = __shfl_sync(0xffffffffu, xv, t);
            float2 w = *(const float2*)&sW[(kk + t) * NHID + 2 * lane];
            acc0 += xs * w.x;
            acc1 += xs * w.y;
        }
    }
    float2 r = make_float2(acc0, acc1);
    *(float2*)&out[(size_t)warp * NHID + 2 * lane] = r;
}

// ---------------------------------------------------------------------------
// Scatter stage 1: agg1[dst] += w * sup1[src], 64 floats/edge.
// 16 threads per edge, each handles one float4; vector red.global.add.v4.f32.
// ---------------------------------------------------------------------------
__global__ void scatter1_kernel(const int* __restrict__ src,
                                const int* __restrict__ dst,
                                const float* __restrict__ ew,
                                const float4* __restrict__ sup,
                                float4* __restrict__ agg, int E) {
    int gid = blockIdx.x * blockDim.x + threadIdx.x;
    int e = gid >> 4;
    if (e >= E) return;
    int c = gid & 15;
    int s = src[e], d = dst[e];
    float w = ew[e];
    float4 v = sup[(size_t)s * 16 + c];
    float4* p = agg + (size_t)d * 16 + c;
    asm volatile("red.global.add.v4.f32 [%0], {%1,%2,%3,%4};"
                 :: "l"(p), "f"(w * v.x), "f"(w * v.y), "f"(w * v.z), "f"(w * v.w)
                 : "memory");
}

// ---------------------------------------------------------------------------
// GEMM2: sup2[N,16] = relu(agg1 + b1)[N,64] @ W2[64,16]. Half-warp per row.
// ---------------------------------------------------------------------------
__global__ void gemm2_kernel(const float* __restrict__ agg1,
                             const float* __restrict__ b1,
                             const float* __restrict__ W2,
                             float* __restrict__ out, int N) {
    __shared__ float sW[NHID * NCLASS];  // 4 KB
    __shared__ float sb1[NHID];
    for (int i = threadIdx.x; i < NHID * NCLASS; i += blockDim.x) sW[i] = W2[i];
    if (threadIdx.x < NHID) sb1[threadIdx.x] = b1[threadIdx.x];
    __syncthreads();

    int warp = (blockIdx.x * blockDim.x + threadIdx.x) >> 5;
    int lane = threadIdx.x & 31;
    int half = lane >> 4, l16 = lane & 15;
    int row = warp * 2 + half;
    if (row >= N) return;

    float hv[4];
#pragma unroll
    for (int j = 0; j < 4; j++) {
        int col = j * 16 + l16;
        float v = agg1[(size_t)row * NHID + col] + sb1[col];
        hv[j] = v > 0.f ? v : 0.f;
    }
    float acc = 0.f;
#pragma unroll
    for (int j = 0; j < 4; j++) {
#pragma unroll
        for (int t = 0; t < 16; t++) {
            float xs = __shfl_sync(0xffffffffu, hv[j], t, 16);  // within 16-lane segment
            acc += xs * sW[(j * 16 + t) * NCLASS + l16];
        }
    }
    out[(size_t)row * NCLASS + l16] = acc;
}

// ---------------------------------------------------------------------------
// Scatter stage 2: agg2[dst] += w * sup2[src], 16 floats/edge. 4 threads/edge.
// ---------------------------------------------------------------------------
__global__ void scatter2_kernel(const int* __restrict__ src,
                                const int* __restrict__ dst,
                                const float* __restrict__ ew,
                                const float4* __restrict__ sup,
                                float4* __restrict__ agg, int E) {
    int gid = blockIdx.x * blockDim.x + threadIdx.x;
    int e = gid >> 2;
    if (e >= E) return;
    int c = gid & 3;
    int s = src[e], d = dst[e];
    float w = ew[e];
    float4 v = sup[(size_t)s * 4 + c];
    float4* p = agg + (size_t)d * 4 + c;
    asm volatile("red.global.add.v4.f32 [%0], {%1,%2,%3,%4};"
                 :: "l"(p), "f"(w * v.x), "f"(w * v.y), "f"(w * v.z), "f"(w * v.w)
                 : "memory");
}

// ---------------------------------------------------------------------------
// Finalize: out = log_softmax(agg2 + b2) per row of 16. One thread per row.
// ---------------------------------------------------------------------------
__global__ void finalize_kernel(const float4* __restrict__ agg2,
                                const float* __restrict__ b2,
                                float* __restrict__ out, int N) {
    __shared__ float sb[NCLASS];
    if (threadIdx.x < NCLASS) sb[threadIdx.x] = b2[threadIdx.x];
    __syncthreads();
    int i = blockIdx.x * blockDim.x + threadIdx.x;
    if (i >= N) return;

    float v[NCLASS];
#pragma unroll
    for (int j = 0; j < 4; j++) {
        float4 a = agg2[(size_t)i * 4 + j];
        v[j * 4 + 0] = a.x + sb[j * 4 + 0];
        v[j * 4 + 1] = a.y + sb[j * 4 + 1];
        v[j * 4 + 2] = a.z + sb[j * 4 + 2];
        v[j * 4 + 3] = a.w + sb[j * 4 + 3];
    }
    float m = v[0];
#pragma unroll
    for (int j = 1; j < NCLASS; j++) m = fmaxf(m, v[j]);
    float s = 0.f;
#pragma unroll
    for (int j = 0; j < NCLASS; j++) s += expf(v[j] - m);
    float lse = m + logf(s);
    float4* o = (float4*)out + (size_t)i * 4;
#pragma unroll
    for (int j = 0; j < 4; j++) {
        float4 r = make_float4(v[j * 4 + 0] - lse, v[j * 4 + 1] - lse,
                               v[j * 4 + 2] - lse, v[j * 4 + 3] - lse);
        o[j] = r;
    }
}

extern "C" void kernel_launch(void* const* d_in, const int* in_sizes, int n_in,
                              void* d_out, int out_size) {
    const float* x  = (const float*)d_in[0];
    const int*   src = (const int*)d_in[1];
    const int*   dst = (const int*)d_in[2];
    const float* ew  = (const float*)d_in[3];
    const float* W1  = (const float*)d_in[4];
    const float* b1  = (const float*)d_in[5];
    const float* W2  = (const float*)d_in[6];
    const float* b2  = (const float*)d_in[7];
    float* out = (float*)d_out;

    int N = in_sizes[0] / NFEAT;   // 100000
    int E = in_sizes[1];           // 1600000

    void *p_sup1, *p_agg1, *p_sup2, *p_agg2;
    cudaGetSymbolAddress(&p_sup1, g_sup1);
    cudaGetSymbolAddress(&p_agg1, g_agg1);
    cudaGetSymbolAddress(&p_sup2, g_sup2);
    cudaGetSymbolAddress(&p_agg2, g_agg2);

    // Zero the accumulation buffers (graph-capturable memset nodes).
    cudaMemsetAsync(p_agg1, 0, (size_t)N * NHID * sizeof(float));
    cudaMemsetAsync(p_agg2, 0, (size_t)N * NCLASS * sizeof(float));

    // 1) sup1 = x @ W1
    {
        int warps_per_block = 8;
        int blocks = (N + warps_per_block - 1) / warps_per_block;
        gemm1_kernel<<<blocks, warps_per_block * 32>>>(x, W1, (float*)p_sup1, N);
    }
    // 2) agg1 = adj @ sup1
    {
        long long threads = (long long)E * 16;
        int blocks = (int)((threads + 255) / 256);
        scatter1_kernel<<<blocks, 256>>>(src, dst, ew, (const float4*)p_sup1,
                                         (float4*)p_agg1, E);
    }
    // 3) sup2 = relu(agg1 + b1) @ W2
    {
        int rows_per_block = 16;  // 8 warps * 2 rows
        int blocks = (N + rows_per_block - 1) / rows_per_block;
        gemm2_kernel<<<blocks, 256>>>((const float*)p_agg1, b1, W2,
                                      (float*)p_sup2, N);
    }
    // 4) agg2 = adj @ sup2
    {
        long long threads = (long long)E * 4;
        int blocks = (int)((threads + 255) / 256);
        scatter2_kernel<<<blocks, 256>>>(src, dst, ew, (const float4*)p_sup2,
                                         (float4*)p_agg2, E);
    }
    // 5) out = log_softmax(agg2 + b2)
    {
        int blocks = (N + 255) / 256;
        finalize_kernel<<<blocks, 256>>>((const float4*)p_agg2, b2, out, N);
    }
}

// round 2
// speedup vs baseline: 1.3330x; 1.3330x over previous
#include <cuda_runtime.h>
#include <cuda_bf16.h>
#include <math.h>

// Problem constants (fixed by the dataset)
#define NNODES 100000
#define NFEAT  128
#define NHID   64
#define NCLASS 16

// Scratch: float4 arrays guarantee 16B alignment for vector red.
__device__ float4 g_sup1[NNODES * (NHID / 4)];    // N x 64  (x @ W1)
__device__ float4 g_agg1[NNODES * (NHID / 4)];    // N x 64  (adj @ sup1)
__device__ float4 g_sup2[NNODES * (NCLASS / 4)];  // N x 16  (h @ W2)
__device__ float4 g_agg2[NNODES * (NCLASS / 4)];  // N x 16  (adj @ sup2)

// ---------------------------------------------------------------------------
// GEMM1: out[N,64] = x[N,128] @ W1[128,64].
// Tiled: 64 rows x 64 cols per block, K processed in two 64-wide phases.
// 256 threads, each computes a 4x4 microtile. Static smem = 33.4 KB.
// ---------------------------------------------------------------------------
#define G1_KC 64
__global__ void __launch_bounds__(256) gemm1_kernel(
        const float* __restrict__ x,
        const float* __restrict__ W1,
        float* __restrict__ out, int N) {
    __shared__ float sA[64][G1_KC + 4];   // +4 pad: keeps float4 align, kills bank conflicts
    __shared__ float sB[G1_KC][64];

    int tid = threadIdx.x;
    int rb = blockIdx.x * 64;
    int r0 = (tid >> 4) * 4;      // 0..60
    int c0 = (tid & 15) * 4;      // 0..60

    float acc[4][4];
#pragma unroll
    for (int i = 0; i < 4; i++)
#pragma unroll
        for (int j = 0; j < 4; j++) acc[i][j] = 0.f;

#pragma unroll
    for (int kb = 0; kb < NFEAT; kb += G1_KC) {
        // load A tile: 64 rows x 64 ks = 1024 float4, 4 per thread
#pragma unroll
        for (int it = 0; it < 4; it++) {
            int idx = tid + it * 256;          // 0..1023
            int row = idx >> 4;                // /16
            int cc = (idx & 15) * 4;
            float4 v = make_float4(0.f, 0.f, 0.f, 0.f);
            if (rb + row < N)
                v = *(const float4*)&x[(size_t)(rb + row) * NFEAT + kb + cc];
            *(float4*)&sA[row][cc] = v;
        }
        // load B tile: 64 ks x 64 cols = 1024 float4
#pragma unroll
        for (int it = 0; it < 4; it++) {
            int idx = tid + it * 256;
            int k = idx >> 4;
            int cc = (idx & 15) * 4;
            *(float4*)&sB[k][cc] = *(const float4*)&W1[(size_t)(kb + k) * NHID + cc];
        }
        __syncthreads();

#pragma unroll 8
        for (int k = 0; k < G1_KC; k++) {
            float4 b = *(const float4*)&sB[k][c0];
            float a0 = sA[r0 + 0][k];
            float a1 = sA[r0 + 1][k];
            float a2 = sA[r0 + 2][k];
            float a3 = sA[r0 + 3][k];
            acc[0][0] += a0 * b.x; acc[0][1] += a0 * b.y; acc[0][2] += a0 * b.z; acc[0][3] += a0 * b.w;
            acc[1][0] += a1 * b.x; acc[1][1] += a1 * b.y; acc[1][2] += a1 * b.z; acc[1][3] += a1 * b.w;
            acc[2][0] += a2 * b.x; acc[2][1] += a2 * b.y; acc[2][2] += a2 * b.z; acc[2][3] += a2 * b.w;
            acc[3][0] += a3 * b.x; acc[3][1] += a3 * b.y; acc[3][2] += a3 * b.z; acc[3][3] += a3 * b.w;
        }
        __syncthreads();
    }

#pragma unroll
    for (int i = 0; i < 4; i++) {
        int row = rb + r0 + i;
        if (row < N) {
            float4 r = make_float4(acc[i][0], acc[i][1], acc[i][2], acc[i][3]);
            *(float4*)&out[(size_t)row * NHID + c0] = r;
        }
    }
}

// ---------------------------------------------------------------------------
// Scatter stage 1: agg1[dst] += w * sup1[src], 64 floats/edge.
// 4 threads per edge; each thread handles 4 consecutive float4s (64B) with
// 4 independent vector REDs (good MLP, few redundant index loads).
// ---------------------------------------------------------------------------
__global__ void __launch_bounds__(256) scatter1_kernel(
        const int* __restrict__ src,
        const int* __restrict__ dst,
        const float* __restrict__ ew,
        const float4* __restrict__ sup,
        float4* __restrict__ agg, int E) {
    int gid = blockIdx.x * blockDim.x + threadIdx.x;
    int e = gid >> 2;
    if (e >= E) return;
    int c = (gid & 3) * 4;
    int s = src[e], d = dst[e];
    float w = ew[e];
    const float4* vp = sup + (size_t)s * 16 + c;
    float4 v0 = vp[0], v1 = vp[1], v2 = vp[2], v3 = vp[3];
    float4* p = agg + (size_t)d * 16 + c;
    asm volatile("red.global.add.v4.f32 [%0], {%1,%2,%3,%4};"
                 :: "l"(p + 0), "f"(w * v0.x), "f"(w * v0.y), "f"(w * v0.z), "f"(w * v0.w) : "memory");
    asm volatile("red.global.add.v4.f32 [%0], {%1,%2,%3,%4};"
                 :: "l"(p + 1), "f"(w * v1.x), "f"(w * v1.y), "f"(w * v1.z), "f"(w * v1.w) : "memory");
    asm volatile("red.global.add.v4.f32 [%0], {%1,%2,%3,%4};"
                 :: "l"(p + 2), "f"(w * v2.x), "f"(w * v2.y), "f"(w * v2.z), "f"(w * v2.w) : "memory");
    asm volatile("red.global.add.v4.f32 [%0], {%1,%2,%3,%4};"
                 :: "l"(p + 3), "f"(w * v3.x), "f"(w * v3.y), "f"(w * v3.z), "f"(w * v3.w) : "memory");
}

// ---------------------------------------------------------------------------
// GEMM2: sup2[N,16] = relu(agg1 + b1)[N,64] @ W2[64,16]. Half-warp per row.
// ---------------------------------------------------------------------------
__global__ void gemm2_kernel(const float* __restrict__ agg1,
                             const float* __restrict__ b1,
                             const float* __restrict__ W2,
                             float* __restrict__ out, int N) {
    __shared__ float sW[NHID * NCLASS];  // 4 KB
    __shared__ float sb1[NHID];
    for (int i = threadIdx.x; i < NHID * NCLASS; i += blockDim.x) sW[i] = W2[i];
    if (threadIdx.x < NHID) sb1[threadIdx.x] = b1[threadIdx.x];
    __syncthreads();

    int warp = (blockIdx.x * blockDim.x + threadIdx.x) >> 5;
    int lane = threadIdx.x & 31;
    int half = lane >> 4, l16 = lane & 15;
    int row = warp * 2 + half;
    if (row >= N) return;

    float hv[4];
#pragma unroll
    for (int j = 0; j < 4; j++) {
        int col = j * 16 + l16;
        float v = agg1[(size_t)row * NHID + col] + sb1[col];
        hv[j] = v > 0.f ? v : 0.f;
    }
    float acc = 0.f;
#pragma unroll
    for (int j = 0; j < 4; j++) {
#pragma unroll
        for (int t = 0; t < 16; t++) {
            float xs = __shfl_sync(0xffffffffu, hv[j], t, 16);  // within 16-lane segment
            acc += xs * sW[(j * 16 + t) * NCLASS + l16];
        }
    }
    out[(size_t)row * NCLASS + l16] = acc;
}

// ---------------------------------------------------------------------------
// Scatter stage 2: agg2[dst] += w * sup2[src], 16 floats/edge.
// One thread per edge: perfectly coalesced index loads, 4 vector REDs.
// ---------------------------------------------------------------------------
__global__ void __launch_bounds__(256) scatter2_kernel(
        const int* __restrict__ src,
        const int* __restrict__ dst,
        const float* __restrict__ ew,
        const float4* __restrict__ sup,
        float4* __restrict__ agg, int E) {
    int e = blockIdx.x * blockDim.x + threadIdx.x;
    if (e >= E) return;
    int s = src[e], d = dst[e];
    float w = ew[e];
    const float4* vp = sup + (size_t)s * 4;
    float4 v0 = vp[0], v1 = vp[1], v2 = vp[2], v3 = vp[3];
    float4* p = agg + (size_t)d * 4;
    asm volatile("red.global.add.v4.f32 [%0], {%1,%2,%3,%4};"
                 :: "l"(p + 0), "f"(w * v0.x), "f"(w * v0.y), "f"(w * v0.z), "f"(w * v0.w) : "memory");
    asm volatile("red.global.add.v4.f32 [%0], {%1,%2,%3,%4};"
                 :: "l"(p + 1), "f"(w * v1.x), "f"(w * v1.y), "f"(w * v1.z), "f"(w * v1.w) : "memory");
    asm volatile("red.global.add.v4.f32 [%0], {%1,%2,%3,%4};"
                 :: "l"(p + 2), "f"(w * v2.x), "f"(w * v2.y), "f"(w * v2.z), "f"(w * v2.w) : "memory");
    asm volatile("red.global.add.v4.f32 [%0], {%1,%2,%3,%4};"
                 :: "l"(p + 3), "f"(w * v3.x), "f"(w * v3.y), "f"(w * v3.z), "f"(w * v3.w) : "memory");
}

// ---------------------------------------------------------------------------
// Finalize: out = log_softmax(agg2 + b2) per row of 16. One thread per row.
// ---------------------------------------------------------------------------
__global__ void finalize_kernel(const float4* __restrict__ agg2,
                                const float* __restrict__ b2,
                                float* __restrict__ out, int N) {
    __shared__ float sb[NCLASS];
    if (threadIdx.x < NCLASS) sb[threadIdx.x] = b2[threadIdx.x];
    __syncthreads();
    int i = blockIdx.x * blockDim.x + threadIdx.x;
    if (i >= N) return;

    float v[NCLASS];
#pragma unroll
    for (int j = 0; j < 4; j++) {
        float4 a = agg2[(size_t)i * 4 + j];
        v[j * 4 + 0] = a.x + sb[j * 4 + 0];
        v[j * 4 + 1] = a.y + sb[j * 4 + 1];
        v[j * 4 + 2] = a.z + sb[j * 4 + 2];
        v[j * 4 + 3] = a.w + sb[j * 4 + 3];
    }
    float m = v[0];
#pragma unroll
    for (int j = 1; j < NCLASS; j++) m = fmaxf(m, v[j]);
    float s = 0.f;
#pragma unroll
    for (int j = 0; j < NCLASS; j++) s += expf(v[j] - m);
    float lse = m + logf(s);
    float4* o = (float4*)out + (size_t)i * 4;
#pragma unroll
    for (int j = 0; j < 4; j++) {
        float4 r = make_float4(v[j * 4 + 0] - lse, v[j * 4 + 1] - lse,
                               v[j * 4 + 2] - lse, v[j * 4 + 3] - lse);
        o[j] = r;
    }
}

extern "C" void kernel_launch(void* const* d_in, const int* in_sizes, int n_in,
                              void* d_out, int out_size) {
    const float* x  = (const float*)d_in[0];
    const int*   src = (const int*)d_in[1];
    const int*   dst = (const int*)d_in[2];
    const float* ew  = (const float*)d_in[3];
    const float* W1  = (const float*)d_in[4];
    const float* b1  = (const float*)d_in[5];
    const float* W2  = (const float*)d_in[6];
    const float* b2  = (const float*)d_in[7];
    float* out = (float*)d_out;

    int N = in_sizes[0] / NFEAT;   // 100000
    int E = in_sizes[1];           // 1600000

    void *p_sup1, *p_agg1, *p_sup2, *p_agg2;
    cudaGetSymbolAddress(&p_sup1, g_sup1);
    cudaGetSymbolAddress(&p_agg1, g_agg1);
    cudaGetSymbolAddress(&p_sup2, g_sup2);
    cudaGetSymbolAddress(&p_agg2, g_agg2);

    // Zero the accumulation buffers (graph-capturable memset nodes).
    cudaMemsetAsync(p_agg1, 0, (size_t)N * NHID * sizeof(float));
    cudaMemsetAsync(p_agg2, 0, (size_t)N * NCLASS * sizeof(float));

    // 1) sup1 = x @ W1 (tiled 64x64)
    {
        int blocks = (N + 63) / 64;
        gemm1_kernel<<<blocks, 256>>>(x, W1, (float*)p_sup1, N);
    }
    // 2) agg1 = adj @ sup1  (4 threads/edge)
    {
        long long threads = (long long)E * 4;
        int blocks = (int)((threads + 255) / 256);
        scatter1_kernel<<<blocks, 256>>>(src, dst, ew, (const float4*)p_sup1,
                                         (float4*)p_agg1, E);
    }
    // 3) sup2 = relu(agg1 + b1) @ W2
    {
        int rows_per_block = 16;  // 8 warps * 2 rows
        int blocks = (N + rows_per_block - 1) / rows_per_block;
        gemm2_kernel<<<blocks, 256>>>((const float*)p_agg1, b1, W2,
                                      (float*)p_sup2, N);
    }
    // 4) agg2 = adj @ sup2  (1 thread/edge)
    {
        int blocks = (E + 255) / 256;
        scatter2_kernel<<<blocks, 256>>>(src, dst, ew, (const float4*)p_sup2,
                                         (float4*)p_agg2, E);
    }
    // 5) out = log_softmax(agg2 + b2)
    {
        int blocks = (N + 255) / 256;
        finalize_kernel<<<blocks, 256>>>((const float4*)p_agg2, b2, out, N);
    }
}

// round 3
// speedup vs baseline: 1.3459x; 1.0097x over previous
#include <cuda_runtime.h>
#include <cuda_fp16.h>
#include <cuda_bf16.h>
#include <math.h>

// Problem constants (fixed by the dataset)
#define NNODES 100000
#define NFEAT  128
#define NHID   64
#define NCLASS 16

// Scratch buffers. fp16 payload for stage-1 gather (row = 128B), fp32 elsewhere.
__device__ __align__(128) uint4  g_sup1h[NNODES * 8];           // N x 64 fp16 (x @ W1)
__device__ __align__(128) float4 g_agg1[NNODES * (NHID / 4)];   // N x 64 f32
__device__ __align__(128) float4 g_sup2[NNODES * (NCLASS / 4)]; // N x 16 f32
__device__ __align__(128) float4 g_agg2[NNODES * (NCLASS / 4)]; // N x 16 f32

// ---------------------------------------------------------------------------
// GEMM1: sup1[N,64] = x[N,128] @ W1[128,64], output fp16x2.
// 128x64 block tile, KC=32 (4 phases), 256 threads, 4x8 microtile.
// Inner product uses packed fma.rn.f32x2 (FFMA2) — 2 FLOP-pairs per issue.
// ---------------------------------------------------------------------------
#define G1_KC 32
__global__ void __launch_bounds__(256) gemm1_kernel(
        const float* __restrict__ x,
        const float* __restrict__ W1,
        uint4* __restrict__ outh, int N) {
    __shared__ float sA[G1_KC][132];   // k-major (transposed) A tile, padded
    __shared__ float sB[G1_KC][64];

    int tid = threadIdx.x;
    int rb = blockIdx.x * 128;
    int r0 = (tid >> 3) * 4;          // 0..124
    int c0 = (tid & 7) * 8;           // 0..56

    unsigned long long acc[4][4];     // 4 rows x 4 f32x2-pairs (8 cols)
#pragma unroll
    for (int i = 0; i < 4; i++)
#pragma unroll
        for (int j = 0; j < 4; j++) acc[i][j] = 0ull;

#pragma unroll
    for (int kb = 0; kb < NFEAT; kb += G1_KC) {
        // A tile: 128 rows x 32 k = 1024 float4 loads, stored transposed
#pragma unroll
        for (int it = 0; it < 4; it++) {
            int idx = tid + it * 256;
            int row = idx >> 3;
            int cc = (idx & 7) * 4;
            float4 v = make_float4(0.f, 0.f, 0.f, 0.f);
            if (rb + row < N)
                v = *(const float4*)&x[(size_t)(rb + row) * NFEAT + kb + cc];
            sA[cc + 0][row] = v.x;
            sA[cc + 1][row] = v.y;
            sA[cc + 2][row] = v.z;
            sA[cc + 3][row] = v.w;
        }
        // B tile: 32 k x 64 cols = 512 float4 loads
#pragma unroll
        for (int it = 0; it < 2; it++) {
            int idx = tid + it * 256;
            int k = idx >> 4;
            int cc = (idx & 15) * 4;
            *(float4*)&sB[k][cc] = *(const float4*)&W1[(size_t)(kb + k) * NHID + cc];
        }
        __syncthreads();

#pragma unroll 8
        for (int k = 0; k < G1_KC; k++) {
            float4 av = *(const float4*)&sA[k][r0];          // a for 4 rows
            ulonglong2 bA = *(const ulonglong2*)&sB[k][c0];      // cols c0..c0+3
            ulonglong2 bB = *(const ulonglong2*)&sB[k][c0 + 4];  // cols c0+4..c0+7
            float ar[4] = {av.x, av.y, av.z, av.w};
#pragma unroll
            for (int i = 0; i < 4; i++) {
                unsigned long long ap;
                asm("mov.b64 %0, {%1, %1};" : "=l"(ap) : "f"(ar[i]));
                asm("fma.rn.f32x2 %0, %1, %2, %0;" : "+l"(acc[i][0]) : "l"(ap), "l"(bA.x));
                asm("fma.rn.f32x2 %0, %1, %2, %0;" : "+l"(acc[i][1]) : "l"(ap), "l"(bA.y));
                asm("fma.rn.f32x2 %0, %1, %2, %0;" : "+l"(acc[i][2]) : "l"(ap), "l"(bB.x));
                asm("fma.rn.f32x2 %0, %1, %2, %0;" : "+l"(acc[i][3]) : "l"(ap), "l"(bB.y));
            }
        }
        __syncthreads();
    }

    // Epilogue: convert 8 f32 per row to 4 half2, one uint4 store per row.
#pragma unroll
    for (int i = 0; i < 4; i++) {
        int row = rb + r0 + i;
        if (row < N) {
            uint4 o;
            unsigned r01, r23, r45, r67;
            float2 f0 = *(float2*)&acc[i][0];
            float2 f1 = *(float2*)&acc[i][1];
            float2 f2 = *(float2*)&acc[i][2];
            float2 f3 = *(float2*)&acc[i][3];
            __half2 h0 = __floats2half2_rn(f0.x, f0.y);
            __half2 h1 = __floats2half2_rn(f1.x, f1.y);
            __half2 h2 = __floats2half2_rn(f2.x, f2.y);
            __half2 h3 = __floats2half2_rn(f3.x, f3.y);
            r01 = *(unsigned*)&h0; r23 = *(unsigned*)&h1;
            r45 = *(unsigned*)&h2; r67 = *(unsigned*)&h3;
            o.x = r01; o.y = r23; o.z = r45; o.w = r67;
            outh[(size_t)row * 8 + (c0 >> 3)] = o;
        }
    }
}

// ---------------------------------------------------------------------------
// Scatter stage 1: agg1[dst] += w * sup1[src], 64 values/edge, fp16 gather.
// 4 threads/edge; each thread gathers 32B (2 x uint4 = 16 halves), converts
// to f32, and issues 4 vector REDs (64B).
// ---------------------------------------------------------------------------
__device__ __forceinline__ float4 h4_to_f4(unsigned a, unsigned b, float w) {
    float2 fa = __half22float2(*(__half2*)&a);
    float2 fb = __half22float2(*(__half2*)&b);
    return make_float4(fa.x * w, fa.y * w, fb.x * w, fb.y * w);
}

__global__ void __launch_bounds__(256) scatter1_kernel(
        const int* __restrict__ src,
        const int* __restrict__ dst,
        const float* __restrict__ ew,
        const uint4* __restrict__ suph,
        float4* __restrict__ agg, int E) {
    int gid = blockIdx.x * blockDim.x + threadIdx.x;
    int e = gid >> 2;
    if (e >= E) return;
    int c = gid & 3;
    int s = src[e], d = dst[e];
    float w = ew[e];
    const uint4* vp = suph + (size_t)s * 8 + c * 2;
    uint4 u0 = vp[0], u1 = vp[1];
    float4 m0 = h4_to_f4(u0.x, u0.y, w);
    float4 m1 = h4_to_f4(u0.z, u0.w, w);
    float4 m2 = h4_to_f4(u1.x, u1.y, w);
    float4 m3 = h4_to_f4(u1.z, u1.w, w);
    float4* p = agg + (size_t)d * 16 + c * 4;
    asm volatile("red.global.add.v4.f32 [%0], {%1,%2,%3,%4};"
                 :: "l"(p + 0), "f"(m0.x), "f"(m0.y), "f"(m0.z), "f"(m0.w) : "memory");
    asm volatile("red.global.add.v4.f32 [%0], {%1,%2,%3,%4};"
                 :: "l"(p + 1), "f"(m1.x), "f"(m1.y), "f"(m1.z), "f"(m1.w) : "memory");
    asm volatile("red.global.add.v4.f32 [%0], {%1,%2,%3,%4};"
                 :: "l"(p + 2), "f"(m2.x), "f"(m2.y), "f"(m2.z), "f"(m2.w) : "memory");
    asm volatile("red.global.add.v4.f32 [%0], {%1,%2,%3,%4};"
                 :: "l"(p + 3), "f"(m3.x), "f"(m3.y), "f"(m3.z), "f"(m3.w) : "memory");
}

// ---------------------------------------------------------------------------
// GEMM2: sup2[N,16] = relu(agg1 + b1)[N,64] @ W2[64,16]. Half-warp per row.
// ---------------------------------------------------------------------------
__global__ void gemm2_kernel(const float* __restrict__ agg1,
                             const float* __restrict__ b1,
                             const float* __restrict__ W2,
                             float* __restrict__ out, int N) {
    __shared__ float sW[NHID * NCLASS];  // 4 KB
    __shared__ float sb1[NHID];
    for (int i = threadIdx.x; i < NHID * NCLASS; i += blockDim.x) sW[i] = W2[i];
    if (threadIdx.x < NHID) sb1[threadIdx.x] = b1[threadIdx.x];
    __syncthreads();

    int warp = (blockIdx.x * blockDim.x + threadIdx.x) >> 5;
    int lane = threadIdx.x & 31;
    int half = lane >> 4, l16 = lane & 15;
    int row = warp * 2 + half;
    if (row >= N) return;

    float hv[4];
#pragma unroll
    for (int j = 0; j < 4; j++) {
        int col = j * 16 + l16;
        float v = agg1[(size_t)row * NHID + col] + sb1[col];
        hv[j] = v > 0.f ? v : 0.f;
    }
    float acc = 0.f;
#pragma unroll
    for (int j = 0; j < 4; j++) {
#pragma unroll
        for (int t = 0; t < 16; t++) {
            float xs = __shfl_sync(0xffffffffu, hv[j], t, 16);  // within 16-lane segment
            acc += xs * sW[(j * 16 + t) * NCLASS + l16];
        }
    }
    out[(size_t)row * NCLASS + l16] = acc;
}

// ---------------------------------------------------------------------------
// Scatter stage 2: agg2[dst] += w * sup2[src], 16 floats/edge.
// 4 threads/edge, one float4 each (coalesced per-edge rows). R1 layout.
// ---------------------------------------------------------------------------
__global__ void __launch_bounds__(256) scatter2_kernel(
        const int* __restrict__ src,
        const int* __restrict__ dst,
        const float* __restrict__ ew,
        const float4* __restrict__ sup,
        float4* __restrict__ agg, int E) {
    int gid = blockIdx.x * blockDim.x + threadIdx.x;
    int e = gid >> 2;
    if (e >= E) return;
    int c = gid & 3;
    int s = src[e], d = dst[e];
    float w = ew[e];
    float4 v = sup[(size_t)s * 4 + c];
    float4* p = agg + (size_t)d * 4 + c;
    asm volatile("red.global.add.v4.f32 [%0], {%1,%2,%3,%4};"
                 :: "l"(p), "f"(w * v.x), "f"(w * v.y), "f"(w * v.z), "f"(w * v.w)
                 : "memory");
}

// ---------------------------------------------------------------------------
// Finalize: out = log_softmax(agg2 + b2) per row of 16. One thread per row.
// ---------------------------------------------------------------------------
__global__ void finalize_kernel(const float4* __restrict__ agg2,
                                const float* __restrict__ b2,
                                float* __restrict__ out, int N) {
    __shared__ float sb[NCLASS];
    if (threadIdx.x < NCLASS) sb[threadIdx.x] = b2[threadIdx.x];
    __syncthreads();
    int i = blockIdx.x * blockDim.x + threadIdx.x;
    if (i >= N) return;

    float v[NCLASS];
#pragma unroll
    for (int j = 0; j < 4; j++) {
        float4 a = agg2[(size_t)i * 4 + j];
        v[j * 4 + 0] = a.x + sb[j * 4 + 0];
        v[j * 4 + 1] = a.y + sb[j * 4 + 1];
        v[j * 4 + 2] = a.z + sb[j * 4 + 2];
        v[j * 4 + 3] = a.w + sb[j * 4 + 3];
    }
    float m = v[0];
#pragma unroll
    for (int j = 1; j < NCLASS; j++) m = fmaxf(m, v[j]);
    float s = 0.f;
#pragma unroll
    for (int j = 0; j < NCLASS; j++) s += expf(v[j] - m);
    float lse = m + logf(s);
    float4* o = (float4*)out + (size_t)i * 4;
#pragma unroll
    for (int j = 0; j < 4; j++) {
        float4 r = make_float4(v[j * 4 + 0] - lse, v[j * 4 + 1] - lse,
                               v[j * 4 + 2] - lse, v[j * 4 + 3] - lse);
        o[j] = r;
    }
}

extern "C" void kernel_launch(void* const* d_in, const int* in_sizes, int n_in,
                              void* d_out, int out_size) {
    const float* x  = (const float*)d_in[0];
    const int*   src = (const int*)d_in[1];
    const int*   dst = (const int*)d_in[2];
    const float* ew  = (const float*)d_in[3];
    const float* W1  = (const float*)d_in[4];
    const float* b1  = (const float*)d_in[5];
    const float* W2  = (const float*)d_in[6];
    const float* b2  = (const float*)d_in[7];
    float* out = (float*)d_out;

    int N = in_sizes[0] / NFEAT;   // 100000
    int E = in_sizes[1];           // 1600000

    void *p_sup1h, *p_agg1, *p_sup2, *p_agg2;
    cudaGetSymbolAddress(&p_sup1h, g_sup1h);
    cudaGetSymbolAddress(&p_agg1, g_agg1);
    cudaGetSymbolAddress(&p_sup2, g_sup2);
    cudaGetSymbolAddress(&p_agg2, g_agg2);

    // Zero the accumulation buffers (graph-capturable memset nodes).
    cudaMemsetAsync(p_agg1, 0, (size_t)N * NHID * sizeof(float));
    cudaMemsetAsync(p_agg2, 0, (size_t)N * NCLASS * sizeof(float));

    // 1) sup1 = x @ W1 (fp16 output, FFMA2 inner product)
    {
        int blocks = (N + 127) / 128;
        gemm1_kernel<<<blocks, 256>>>(x, W1, (uint4*)p_sup1h, N);
    }
    // 2) agg1 = adj @ sup1  (4 threads/edge, fp16 gather)
    {
        long long threads = (long long)E * 4;
        int blocks = (int)((threads + 255) / 256);
        scatter1_kernel<<<blocks, 256>>>(src, dst, ew, (const uint4*)p_sup1h,
                                         (float4*)p_agg1, E);
    }
    // 3) sup2 = relu(agg1 + b1) @ W2
    {
        int rows_per_block = 16;  // 8 warps * 2 rows
        int blocks = (N + rows_per_block - 1) / rows_per_block;
        gemm2_kernel<<<blocks, 256>>>((const float*)p_agg1, b1, W2,
                                      (float*)p_sup2, N);
    }
    // 4) agg2 = adj @ sup2  (4 threads/edge)
    {
        long long threads = (long long)E * 4;
        int blocks = (int)((threads + 255) / 256);
        scatter2_kernel<<<blocks, 256>>>(src, dst, ew, (const float4*)p_sup2,
                                         (float4*)p_agg2, E);
    }
    // 5) out = log_softmax(agg2 + b2)
    {
        int blocks = (N + 255) / 256;
        finalize_kernel<<<blocks, 256>>>((const float4*)p_agg2, b2, out, N);
    }
}

// round 4
// speedup vs baseline: 1.5715x; 1.1676x over previous
#include <cuda_runtime.h>
#include <cuda_fp16.h>
#include <cuda_bf16.h>
#include <math.h>

// Problem constants (fixed by the dataset)
#define NNODES 100000
#define MAXE   1600000
#define NFEAT  128
#define NHID   64
#define NCLASS 16

// Scratch buffers.
__device__ __align__(128) uint4  g_sup1h[NNODES * 8];           // N x 64 fp16 (x @ W1)
__device__ __align__(128) float4 g_sup2[NNODES * (NCLASS / 4)]; // N x 16 f32
__device__ int  g_cnt[NNODES];       // degree counts, then cursor
__device__ int  g_off[NNODES + 1];   // CSR offsets
__device__ int2 g_csr[MAXE];         // packed {src, float_as_int(w)}
__device__ int  g_bsum[128];         // scan block sums

// ---------------------------------------------------------------------------
// GEMM1: sup1[N,64] = x[N,128] @ W1[128,64], output fp16x2. (unchanged R3)
// ---------------------------------------------------------------------------
#define G1_KC 32
__global__ void __launch_bounds__(256) gemm1_kernel(
        const float* __restrict__ x,
        const float* __restrict__ W1,
        uint4* __restrict__ outh, int N) {
    __shared__ float sA[G1_KC][132];
    __shared__ float sB[G1_KC][64];

    int tid = threadIdx.x;
    int rb = blockIdx.x * 128;
    int r0 = (tid >> 3) * 4;
    int c0 = (tid & 7) * 8;

    unsigned long long acc[4][4];
#pragma unroll
    for (int i = 0; i < 4; i++)
#pragma unroll
        for (int j = 0; j < 4; j++) acc[i][j] = 0ull;

#pragma unroll
    for (int kb = 0; kb < NFEAT; kb += G1_KC) {
#pragma unroll
        for (int it = 0; it < 4; it++) {
            int idx = tid + it * 256;
            int row = idx >> 3;
            int cc = (idx & 7) * 4;
            float4 v = make_float4(0.f, 0.f, 0.f, 0.f);
            if (rb + row < N)
                v = *(const float4*)&x[(size_t)(rb + row) * NFEAT + kb + cc];
            sA[cc + 0][row] = v.x;
            sA[cc + 1][row] = v.y;
            sA[cc + 2][row] = v.z;
            sA[cc + 3][row] = v.w;
        }
#pragma unroll
        for (int it = 0; it < 2; it++) {
            int idx = tid + it * 256;
            int k = idx >> 4;
            int cc = (idx & 15) * 4;
            *(float4*)&sB[k][cc] = *(const float4*)&W1[(size_t)(kb + k) * NHID + cc];
        }
        __syncthreads();

#pragma unroll 8
        for (int k = 0; k < G1_KC; k++) {
            float4 av = *(const float4*)&sA[k][r0];
            ulonglong2 bA = *(const ulonglong2*)&sB[k][c0];
            ulonglong2 bB = *(const ulonglong2*)&sB[k][c0 + 4];
            float ar[4] = {av.x, av.y, av.z, av.w};
#pragma unroll
            for (int i = 0; i < 4; i++) {
                unsigned long long ap;
                asm("mov.b64 %0, {%1, %1};" : "=l"(ap) : "f"(ar[i]));
                asm("fma.rn.f32x2 %0, %1, %2, %0;" : "+l"(acc[i][0]) : "l"(ap), "l"(bA.x));
                asm("fma.rn.f32x2 %0, %1, %2, %0;" : "+l"(acc[i][1]) : "l"(ap), "l"(bA.y));
                asm("fma.rn.f32x2 %0, %1, %2, %0;" : "+l"(acc[i][2]) : "l"(ap), "l"(bB.x));
                asm("fma.rn.f32x2 %0, %1, %2, %0;" : "+l"(acc[i][3]) : "l"(ap), "l"(bB.y));
            }
        }
        __syncthreads();
    }

#pragma unroll
    for (int i = 0; i < 4; i++) {
        int row = rb + r0 + i;
        if (row < N) {
            uint4 o;
            float2 f0 = *(float2*)&acc[i][0];
            float2 f1 = *(float2*)&acc[i][1];
            float2 f2 = *(float2*)&acc[i][2];
            float2 f3 = *(float2*)&acc[i][3];
            __half2 h0 = __floats2half2_rn(f0.x, f0.y);
            __half2 h1 = __floats2half2_rn(f1.x, f1.y);
            __half2 h2 = __floats2half2_rn(f2.x, f2.y);
            __half2 h3 = __floats2half2_rn(f3.x, f3.y);
            o.x = *(unsigned*)&h0; o.y = *(unsigned*)&h1;
            o.z = *(unsigned*)&h2; o.w = *(unsigned*)&h3;
            outh[(size_t)row * 8 + (c0 >> 3)] = o;
        }
    }
}

// ---------------------------------------------------------------------------
// CSR build: histogram -> exclusive scan (3 phases) -> permute
// ---------------------------------------------------------------------------
__global__ void hist_kernel(const int* __restrict__ dst, int* __restrict__ cnt, int E) {
    int e = blockIdx.x * blockDim.x + threadIdx.x;
    if (e < E) atomicAdd(&cnt[dst[e]], 1);
}

__global__ void __launch_bounds__(1024) scan_k1(const int* __restrict__ cnt,
                                                int* __restrict__ off,
                                                int* __restrict__ bsum, int n) {
    __shared__ int s[1024];
    int i = blockIdx.x * 1024 + threadIdx.x;
    int v = (i < n) ? cnt[i] : 0;
    s[threadIdx.x] = v;
    __syncthreads();
#pragma unroll
    for (int d = 1; d < 1024; d <<= 1) {
        int t = (threadIdx.x >= d) ? s[threadIdx.x - d] : 0;
        __syncthreads();
        s[threadIdx.x] += t;
        __syncthreads();
    }
    if (i < n) off[i] = s[threadIdx.x] - v;   // exclusive
    if (threadIdx.x == 1023) bsum[blockIdx.x] = s[1023];
}

__global__ void __launch_bounds__(128) scan_k2(int* __restrict__ bsum, int nb) {
    __shared__ int s[128];
    int v = (threadIdx.x < nb) ? bsum[threadIdx.x] : 0;
    s[threadIdx.x] = v;
    __syncthreads();
#pragma unroll
    for (int d = 1; d < 128; d <<= 1) {
        int t = (threadIdx.x >= d) ? s[threadIdx.x - d] : 0;
        __syncthreads();
        s[threadIdx.x] += t;
        __syncthreads();
    }
    if (threadIdx.x < nb) bsum[threadIdx.x] = s[threadIdx.x] - v;  // exclusive
}

__global__ void __launch_bounds__(1024) scan_k3(int* __restrict__ off,
                                                const int* __restrict__ bsum,
                                                int n, int E) {
    int i = blockIdx.x * 1024 + threadIdx.x;
    if (i < n) off[i] += bsum[i >> 10];
    if (i == 0) off[n] = E;
}

__global__ void permute_kernel(const int* __restrict__ src,
                               const int* __restrict__ dst,
                               const float* __restrict__ ew,
                               int* __restrict__ cursor,
                               int2* __restrict__ csr, int E) {
    int e = blockIdx.x * blockDim.x + threadIdx.x;
    if (e >= E) return;
    int d = dst[e];
    int pos = atomicAdd(&cursor[d], 1);
    csr[pos] = make_int2(src[e], __float_as_int(ew[e]));
}

// ---------------------------------------------------------------------------
// Gather stage 1 (fused): per node, aggregate fp16 rows of sup1, then
// h = relu(agg + b1), sup2 = h @ W2. One warp per node; lane holds h2 pair.
// ---------------------------------------------------------------------------
__global__ void __launch_bounds__(256) gather1_kernel(
        const int* __restrict__ off,
        const int2* __restrict__ csr,
        const unsigned* __restrict__ suph,   // N x 32 half2 words
        const float* __restrict__ b1,
        const float* __restrict__ W2,
        float* __restrict__ sup2, int N) {
    __shared__ float sW[NHID * NCLASS];  // 4 KB
    __shared__ float sb[NHID];
    for (int i = threadIdx.x; i < NHID * NCLASS; i += blockDim.x) sW[i] = W2[i];
    if (threadIdx.x < NHID) sb[threadIdx.x] = b1[threadIdx.x];
    __syncthreads();

    int warp = (blockIdx.x * blockDim.x + threadIdx.x) >> 5;
    int lane = threadIdx.x & 31;
    if (warp >= N) return;

    int beg = off[warp], end = off[warp + 1];
    float ax = 0.f, ay = 0.f;
    for (int j = beg; j < end; j++) {
        int2 ed = csr[j];                       // broadcast load
        float w = __int_as_float(ed.y);
        unsigned u = suph[(size_t)ed.x * 32 + lane];
        float2 f = __half22float2(*(__half2*)&u);
        ax += w * f.x;
        ay += w * f.y;
    }
    float h0 = fmaxf(ax + sb[2 * lane], 0.f);
    float h1 = fmaxf(ay + sb[2 * lane + 1], 0.f);

    // sup2[c] = sum_k h[k] * W2[k][c];  lane (c = lane&15) accumulates via shfl
    int c = lane & 15;
    float o = 0.f;
#pragma unroll
    for (int t = 0; t < 32; t++) {
        float a0 = __shfl_sync(0xffffffffu, h0, t);
        float a1 = __shfl_sync(0xffffffffu, h1, t);
        o += a0 * sW[(2 * t) * NCLASS + c] + a1 * sW[(2 * t + 1) * NCLASS + c];
    }
    if (lane < 16) sup2[(size_t)warp * NCLASS + lane] = o;
}

// ---------------------------------------------------------------------------
// Gather stage 2 (fused): per node, aggregate sup2 rows, +b2, log_softmax.
// Warp per node; lanes 0-15 handle even edges, 16-31 odd edges.
// ---------------------------------------------------------------------------
__global__ void __launch_bounds__(256) gather2_kernel(
        const int* __restrict__ off,
        const int2* __restrict__ csr,
        const float* __restrict__ sup2,
        const float* __restrict__ b2,
        float* __restrict__ out, int N) {
    int warp = (blockIdx.x * blockDim.x + threadIdx.x) >> 5;
    int lane = threadIdx.x & 31;
    if (warp >= N) return;
    int l16 = lane & 15;
    int half = lane >> 4;

    int beg = off[warp], end = off[warp + 1];
    float acc = 0.f;
    for (int j = beg + half; j < end; j += 2) {
        int2 ed = csr[j];
        float w = __int_as_float(ed.y);
        acc += w * sup2[(size_t)ed.x * NCLASS + l16];
    }
    acc += __shfl_down_sync(0xffffffffu, acc, 16);  // combine halves (valid in lanes<16)

    float v = acc + b2[l16];
    // 16-wide log_softmax via xor shuffles (halves stay separate for m<=8)
    float m = v;
#pragma unroll
    for (int d = 8; d; d >>= 1) m = fmaxf(m, __shfl_xor_sync(0xffffffffu, m, d));
    float ex = expf(v - m);
    float ssum = ex;
#pragma unroll
    for (int d = 8; d; d >>= 1) ssum += __shfl_xor_sync(0xffffffffu, ssum, d);
    float r = v - m - logf(ssum);
    if (lane < 16) out[(size_t)warp * NCLASS + lane] = r;
}

extern "C" void kernel_launch(void* const* d_in, const int* in_sizes, int n_in,
                              void* d_out, int out_size) {
    const float* x  = (const float*)d_in[0];
    const int*   src = (const int*)d_in[1];
    const int*   dst = (const int*)d_in[2];
    const float* ew  = (const float*)d_in[3];
    const float* W1  = (const float*)d_in[4];
    const float* b1  = (const float*)d_in[5];
    const float* W2  = (const float*)d_in[6];
    const float* b2  = (const float*)d_in[7];
    float* out = (float*)d_out;

    int N = in_sizes[0] / NFEAT;   // 100000
    int E = in_sizes[1];           // 1600000

    void *p_sup1h, *p_sup2, *p_cnt, *p_off, *p_csr, *p_bsum;
    cudaGetSymbolAddress(&p_sup1h, g_sup1h);
    cudaGetSymbolAddress(&p_sup2, g_sup2);
    cudaGetSymbolAddress(&p_cnt, g_cnt);
    cudaGetSymbolAddress(&p_off, g_off);
    cudaGetSymbolAddress(&p_csr, g_csr);
    cudaGetSymbolAddress(&p_bsum, g_bsum);

    int nb_scan = (N + 1023) / 1024;   // 98

    // --- CSR build ---
    cudaMemsetAsync(p_cnt, 0, (size_t)N * sizeof(int));
    hist_kernel<<<(E + 255) / 256, 256>>>(dst, (int*)p_cnt, E);
    scan_k1<<<nb_scan, 1024>>>((const int*)p_cnt, (int*)p_off, (int*)p_bsum, N);
    scan_k2<<<1, 128>>>((int*)p_bsum, nb_scan);
    scan_k3<<<nb_scan, 1024>>>((int*)p_off, (const int*)p_bsum, N, E);
    // cursor = copy of offsets (reuse g_cnt)
    cudaMemcpyAsync(p_cnt, p_off, (size_t)N * sizeof(int), cudaMemcpyDeviceToDevice);
    permute_kernel<<<(E + 255) / 256, 256>>>(src, dst, ew, (int*)p_cnt,
                                             (int2*)p_csr, E);

    // --- GEMM1 (overlaps conceptually; stream-serial is fine) ---
    gemm1_kernel<<<(N + 127) / 128, 256>>>(x, W1, (uint4*)p_sup1h, N);

    // --- Layer 1 aggregation + relu + W2 projection (fused) ---
    gather1_kernel<<<(N * 32 + 255) / 256, 256>>>(
        (const int*)p_off, (const int2*)p_csr, (const unsigned*)p_sup1h,
        b1, W2, (float*)p_sup2, N);

    // --- Layer 2 aggregation + bias + log_softmax (fused) ---
    gather2_kernel<<<(N * 32 + 255) / 256, 256>>>(
        (const int*)p_off, (const int2*)p_csr, (const float*)p_sup2,
        b2, out, N);
}

// round 5
// speedup vs baseline: 2.0680x; 1.3159x over previous
#include <cuda_runtime.h>
#include <cuda_fp16.h>
#include <cuda_bf16.h>
#include <mma.h>
#include <math.h>

using namespace nvcuda;

// Problem constants (fixed by the dataset)
#define NNODES 100000
#define MAXE   1600000
#define NFEAT  128
#define NHID   64
#define NCLASS 16

// Scratch buffers.
__device__ __align__(128) uint4  g_sup1h[NNODES * 8];           // N x 64 fp16 (x @ W1)
__device__ __align__(128) float4 g_sup2[NNODES * (NCLASS / 4)]; // N x 16 f32
__device__ int  g_cnt[NNODES];       // degree counts, then cursor
__device__ int  g_off[NNODES + 1];   // CSR offsets
__device__ int2 g_csr[MAXE];         // packed {src, float_as_int(w)}
__device__ int  g_bsum[128];         // scan block sums

// ---------------------------------------------------------------------------
// GEMM1 (HMMA): sup1[N,64] = x[N,128] @ W1[128,64], fp16 inputs, fp32 acc,
// fp16 output. 128x64 block tile, KC=64 (2 phases), 8 warps, warp = 16 rows.
// ---------------------------------------------------------------------------
__global__ void __launch_bounds__(256) gemm1_kernel(
        const float* __restrict__ x,
        const float* __restrict__ W1,
        uint4* __restrict__ outh, int N) {
    __shared__ __align__(16) char smem[32768];
    __half (*sA)[72] = (__half(*)[72])smem;                  // 128 x 72 halves
    __half (*sB)[72] = (__half(*)[72])(smem + 128 * 72 * 2); // 64 x 72 halves
    float (*sO)[64]  = (float(*)[64])smem;                   // epilogue alias

    int tid = threadIdx.x;
    int w = tid >> 5;
    int lane = tid & 31;
    int rb = blockIdx.x * 128;

    wmma::fragment<wmma::accumulator, 16, 16, 16, float> acc[4];
#pragma unroll
    for (int i = 0; i < 4; i++) wmma::fill_fragment(acc[i], 0.f);

#pragma unroll
    for (int kb = 0; kb < NFEAT; kb += 64) {
        // A tile: 128 rows x 64 ks fp32 -> fp16 (2048 float4, 8/thread)
#pragma unroll
        for (int it = 0; it < 8; it++) {
            int idx = tid + it * 256;
            int row = idx >> 4;
            int cc = (idx & 15) * 4;
            float4 v = make_float4(0.f, 0.f, 0.f, 0.f);
            if (rb + row < N)
                v = *(const float4*)&x[(size_t)(rb + row) * NFEAT + kb + cc];
            *(__half2*)&sA[row][cc]     = __floats2half2_rn(v.x, v.y);
            *(__half2*)&sA[row][cc + 2] = __floats2half2_rn(v.z, v.w);
        }
        // B tile: 64 ks x 64 cols (1024 float4, 4/thread)
#pragma unroll
        for (int it = 0; it < 4; it++) {
            int idx = tid + it * 256;
            int row = idx >> 4;
            int cc = (idx & 15) * 4;
            float4 v = *(const float4*)&W1[(size_t)(kb + row) * NHID + cc];
            *(__half2*)&sB[row][cc]     = __floats2half2_rn(v.x, v.y);
            *(__half2*)&sB[row][cc + 2] = __floats2half2_rn(v.z, v.w);
        }
        __syncthreads();

#pragma unroll
        for (int ks = 0; ks < 64; ks += 16) {
            wmma::fragment<wmma::matrix_a, 16, 16, 16, __half, wmma::row_major> fa;
            wmma::load_matrix_sync(fa, &sA[w * 16][ks], 72);
#pragma unroll
            for (int nt = 0; nt < 4; nt++) {
                wmma::fragment<wmma::matrix_b, 16, 16, 16, __half, wmma::row_major> fb;
                wmma::load_matrix_sync(fb, &sB[ks][nt * 16], 72);
                wmma::mma_sync(acc[nt], fa, fb, acc[nt]);
            }
        }
        __syncthreads();
    }

    // Epilogue: dump fp32 accs to smem strip, convert to fp16, vector store.
#pragma unroll
    for (int nt = 0; nt < 4; nt++)
        wmma::store_matrix_sync(&sO[w * 16][nt * 16], acc[nt], 64, wmma::mem_row_major);
    __syncwarp();

#pragma unroll
    for (int q = 0; q < 4; q++) {
        int idx = lane + q * 32;       // 0..127 over strip's 16 rows x 8 uint4
        int r = idx >> 3;
        int c8 = idx & 7;
        int row = rb + w * 16 + r;
        if (row < N) {
            const float* p = &sO[w * 16 + r][c8 * 8];
            __half2 h0 = __floats2half2_rn(p[0], p[1]);
            __half2 h1 = __floats2half2_rn(p[2], p[3]);
            __half2 h2 = __floats2half2_rn(p[4], p[5]);
            __half2 h3 = __floats2half2_rn(p[6], p[7]);
            uint4 o;
            o.x = *(unsigned*)&h0; o.y = *(unsigned*)&h1;
            o.z = *(unsigned*)&h2; o.w = *(unsigned*)&h3;
            outh[(size_t)row * 8 + c8] = o;
        }
    }
}

// ---------------------------------------------------------------------------
// CSR build: histogram -> exclusive scan (3 phases) -> permute
// ---------------------------------------------------------------------------
__global__ void hist_kernel(const int* __restrict__ dst, int* __restrict__ cnt, int E) {
    int e = blockIdx.x * blockDim.x + threadIdx.x;
    if (e < E) atomicAdd(&cnt[dst[e]], 1);
}

__global__ void __launch_bounds__(1024) scan_k1(const int* __restrict__ cnt,
                                                int* __restrict__ off,
                                                int* __restrict__ bsum, int n) {
    __shared__ int s[1024];
    int i = blockIdx.x * 1024 + threadIdx.x;
    int v = (i < n) ? cnt[i] : 0;
    s[threadIdx.x] = v;
    __syncthreads();
#pragma unroll
    for (int d = 1; d < 1024; d <<= 1) {
        int t = (threadIdx.x >= d) ? s[threadIdx.x - d] : 0;
        __syncthreads();
        s[threadIdx.x] += t;
        __syncthreads();
    }
    if (i < n) off[i] = s[threadIdx.x] - v;   // exclusive
    if (threadIdx.x == 1023) bsum[blockIdx.x] = s[1023];
}

__global__ void __launch_bounds__(128) scan_k2(int* __restrict__ bsum, int nb) {
    __shared__ int s[128];
    int v = (threadIdx.x < nb) ? bsum[threadIdx.x] : 0;
    s[threadIdx.x] = v;
    __syncthreads();
#pragma unroll
    for (int d = 1; d < 128; d <<= 1) {
        int t = (threadIdx.x >= d) ? s[threadIdx.x - d] : 0;
        __syncthreads();
        s[threadIdx.x] += t;
        __syncthreads();
    }
    if (threadIdx.x < nb) bsum[threadIdx.x] = s[threadIdx.x] - v;  // exclusive
}

// Finalizes offsets AND initializes the permute cursor (removes a memcpy).
__global__ void __launch_bounds__(1024) scan_k3(int* __restrict__ off,
                                                const int* __restrict__ bsum,
                                                int* __restrict__ cursor,
                                                int n, int E) {
    int i = blockIdx.x * 1024 + threadIdx.x;
    if (i < n) {
        int v = off[i] + bsum[i >> 10];
        off[i] = v;
        cursor[i] = v;
    }
    if (i == 0) off[n] = E;
}

__global__ void permute_kernel(const int* __restrict__ src,
                               const int* __restrict__ dst,
                               const float* __restrict__ ew,
                               int* __restrict__ cursor,
                               int2* __restrict__ csr, int E) {
    int e = blockIdx.x * blockDim.x + threadIdx.x;
    if (e >= E) return;
    int d = dst[e];
    int pos = atomicAdd(&cursor[d], 1);
    csr[pos] = make_int2(src[e], __float_as_int(ew[e]));
}

// ---------------------------------------------------------------------------
// Gather stage 1 (fused): per node, aggregate fp16 rows of sup1, then
// h = relu(agg + b1), sup2 = h @ W2. One warp per node; 4-way unrolled edge
// loop -> 4 independent gathers in flight per lane.
// ---------------------------------------------------------------------------
__global__ void __launch_bounds__(256) gather1_kernel(
        const int* __restrict__ off,
        const int2* __restrict__ csr,
        const unsigned* __restrict__ suph,   // N x 32 half2 words
        const float* __restrict__ b1,
        const float* __restrict__ W2,
        float* __restrict__ sup2, int N) {
    __shared__ float sW[NHID * NCLASS];  // 4 KB
    __shared__ float sb[NHID];
    for (int i = threadIdx.x; i < NHID * NCLASS; i += blockDim.x) sW[i] = W2[i];
    if (threadIdx.x < NHID) sb[threadIdx.x] = b1[threadIdx.x];
    __syncthreads();

    int warp = (blockIdx.x * blockDim.x + threadIdx.x) >> 5;
    int lane = threadIdx.x & 31;
    if (warp >= N) return;

    int beg = off[warp], end = off[warp + 1];
    float ax = 0.f, ay = 0.f;
    int j = beg;
    for (; j + 4 <= end; j += 4) {
        int2 e0 = csr[j], e1 = csr[j + 1], e2 = csr[j + 2], e3 = csr[j + 3];
        unsigned u0 = suph[(size_t)e0.x * 32 + lane];
        unsigned u1 = suph[(size_t)e1.x * 32 + lane];
        unsigned u2 = suph[(size_t)e2.x * 32 + lane];
        unsigned u3 = suph[(size_t)e3.x * 32 + lane];
        float w0 = __int_as_float(e0.y), w1 = __int_as_float(e1.y);
        float w2 = __int_as_float(e2.y), w3 = __int_as_float(e3.y);
        float2 f0 = __half22float2(*(__half2*)&u0);
        float2 f1 = __half22float2(*(__half2*)&u1);
        float2 f2 = __half22float2(*(__half2*)&u2);
        float2 f3 = __half22float2(*(__half2*)&u3);
        ax += w0 * f0.x + w1 * f1.x;
        ay += w0 * f0.y + w1 * f1.y;
        ax += w2 * f2.x + w3 * f3.x;
        ay += w2 * f2.y + w3 * f3.y;
    }
    for (; j < end; j++) {
        int2 ed = csr[j];
        float w = __int_as_float(ed.y);
        unsigned u = suph[(size_t)ed.x * 32 + lane];
        float2 f = __half22float2(*(__half2*)&u);
        ax += w * f.x;
        ay += w * f.y;
    }
    float h0 = fmaxf(ax + sb[2 * lane], 0.f);
    float h1 = fmaxf(ay + sb[2 * lane + 1], 0.f);

    // sup2[c] = sum_k h[k] * W2[k][c];  lane (c = lane&15) accumulates via shfl
    int c = lane & 15;
    float o = 0.f;
#pragma unroll
    for (int t = 0; t < 32; t++) {
        float a0 = __shfl_sync(0xffffffffu, h0, t);
        float a1 = __shfl_sync(0xffffffffu, h1, t);
        o += a0 * sW[(2 * t) * NCLASS + c] + a1 * sW[(2 * t + 1) * NCLASS + c];
    }
    if (lane < 16) sup2[(size_t)warp * NCLASS + lane] = o;
}

// ---------------------------------------------------------------------------
// Gather stage 2 (fused): per node, aggregate sup2 rows, +b2, log_softmax.
// Half-warp per edge slot, 2 slots/warp, unrolled x2 -> 4 edges in flight.
// ---------------------------------------------------------------------------
__global__ void __launch_bounds__(256) gather2_kernel(
        const int* __restrict__ off,
        const int2* __restrict__ csr,
        const float* __restrict__ sup2,
        const float* __restrict__ b2,
        float* __restrict__ out, int N) {
    int warp = (blockIdx.x * blockDim.x + threadIdx.x) >> 5;
    int lane = threadIdx.x & 31;
    if (warp >= N) return;
    int l16 = lane & 15;
    int half = lane >> 4;

    int beg = off[warp], end = off[warp + 1];
    float acc = 0.f;
    int j = beg + half;
    for (; j + 2 < end; j += 4) {     // this half-warp: j and j+2 both valid
        int2 ea = csr[j];
        int2 eb = csr[j + 2];
        float va = sup2[(size_t)ea.x * NCLASS + l16];
        float vb = sup2[(size_t)eb.x * NCLASS + l16];
        acc += __int_as_float(ea.y) * va + __int_as_float(eb.y) * vb;
    }
    for (; j < end; j += 2) {
        int2 ed = csr[j];
        acc += __int_as_float(ed.y) * sup2[(size_t)ed.x * NCLASS + l16];
    }
    acc += __shfl_down_sync(0xffffffffu, acc, 16);  // combine halves (valid lanes<16)

    float v = acc + b2[l16];
    float m = v;
#pragma unroll
    for (int d = 8; d; d >>= 1) m = fmaxf(m, __shfl_xor_sync(0xffffffffu, m, d));
    float ex = expf(v - m);
    float ssum = ex;
#pragma unroll
    for (int d = 8; d; d >>= 1) ssum += __shfl_xor_sync(0xffffffffu, ssum, d);
    float r = v - m - logf(ssum);
    if (lane < 16) out[(size_t)warp * NCLASS + lane] = r;
}

extern "C" void kernel_launch(void* const* d_in, const int* in_sizes, int n_in,
                              void* d_out, int out_size) {
    const float* x  = (const float*)d_in[0];
    const int*   src = (const int*)d_in[1];
    const int*   dst = (const int*)d_in[2];
    const float* ew  = (const float*)d_in[3];
    const float* W1  = (const float*)d_in[4];
    const float* b1  = (const float*)d_in[5];
    const float* W2  = (const float*)d_in[6];
    const float* b2  = (const float*)d_in[7];
    float* out = (float*)d_out;

    int N = in_sizes[0] / NFEAT;   // 100000
    int E = in_sizes[1];           // 1600000

    void *p_sup1h, *p_sup2, *p_cnt, *p_off, *p_csr, *p_bsum;
    cudaGetSymbolAddress(&p_sup1h, g_sup1h);
    cudaGetSymbolAddress(&p_sup2, g_sup2);
    cudaGetSymbolAddress(&p_cnt, g_cnt);
    cudaGetSymbolAddress(&p_off, g_off);
    cudaGetSymbolAddress(&p_csr, g_csr);
    cudaGetSymbolAddress(&p_bsum, g_bsum);

    int nb_scan = (N + 1023) / 1024;   // 98

    // Fork: gemm1 on a side stream, overlapped with the CSR build.
    cudaStream_t s1;
    cudaStreamCreateWithFlags(&s1, cudaStreamNonBlocking);
    cudaEvent_t e0, e1;
    cudaEventCreateWithFlags(&e0, cudaEventDisableTiming);
    cudaEventCreateWithFlags(&e1, cudaEventDisableTiming);

    cudaEventRecord(e0, 0);
    cudaStreamWaitEvent(s1, e0, 0);
    gemm1_kernel<<<(N + 127) / 128, 256, 0, s1>>>(x, W1, (uint4*)p_sup1h, N);
    cudaEventRecord(e1, s1);

    // --- CSR build (main stream) ---
    cudaMemsetAsync(p_cnt, 0, (size_t)N * sizeof(int));
    hist_kernel<<<(E + 255) / 256, 256>>>(dst, (int*)p_cnt, E);
    scan_k1<<<nb_scan, 1024>>>((const int*)p_cnt, (int*)p_off, (int*)p_bsum, N);
    scan_k2<<<1, 128>>>((int*)p_bsum, nb_scan);
    scan_k3<<<nb_scan, 1024>>>((int*)p_off, (const int*)p_bsum, (int*)p_cnt, N, E);
    permute_kernel<<<(E + 255) / 256, 256>>>(src, dst, ew, (int*)p_cnt,
                                             (int2*)p_csr, E);

    // Join: gathers need both CSR and sup1.
    cudaStreamWaitEvent(0, e1, 0);

    gather1_kernel<<<(N * 32 + 255) / 256, 256>>>(
        (const int*)p_off, (const int2*)p_csr, (const unsigned*)p_sup1h,
        b1, W2, (float*)p_sup2, N);

    gather2_kernel<<<(N * 32 + 255) / 256, 256>>>(
        (const int*)p_off, (const int2*)p_csr, (const float*)p_sup2,
        b2, out, N);
}